// round 7
// baseline (speedup 1.0000x reference)
#include <cuda_runtime.h>

#define BB      256
#define MAXLEN  10000
#define NWORDS  (MAXLEN * 9)        // 90000
#define NV4     (NWORDS / 4)        // 22500
#define NATOMS  2000
#define NBONDS  1999
#define NANG    1998
#define NTOR    1997
#define NBT     50
#define NAT     100
#define NTT     200
#define EPSF    1e-8f
#define NTHR    1024

#define N_COORD (3 * NATOMS)        // 6000 floats
#define N_BOND  (3 * NBONDS)        // 5997 shorts
#define N_ANGW  (4 * NANG)          // 7992 shorts
#define N_TORW  (5 * NTOR)          // 9985 shorts

// dynamic smem byte offsets
#define OFF_COORD 0
#define OFF_WARP  (OFF_COORD + N_COORD * 4)      // 24000
#define OFF_BK    (OFF_WARP + 32 * 4)            // 24128
#define OFF_BR0   (OFF_BK  + NBT * 4)            // 24328
#define OFF_AK    (OFF_BR0 + NBT * 4)            // 24528
#define OFF_AT0   (OFF_AK  + NAT * 4)            // 24928
#define OFF_TK    (OFF_AT0 + NAT * 4)            // 25328
#define OFF_TC0   (OFF_TK  + NTT * 4)            // 26128
#define OFF_TS0   (OFF_TC0 + NTT * 4)            // 26928
#define OFF_TN    (OFF_TS0 + NTT * 4)            // 27728
#define OFF_SBOND (OFF_TN  + NTT * 4)            // 28528
#define OFF_SANG  (OFF_SBOND + N_BOND * 2)       // 40522
#define OFF_STOR  (OFF_SANG  + N_ANGW * 2)       // 56506
#define SMEM_BYTES (OFF_STOR + N_TORW * 2 + 8)   // 76484

__device__ __forceinline__ void demux(const float4& A, const float4& Bv, int p,
                                      float& v5, float& v6, float& v7, float& v8)
{
    v5 = (p == 0) ? A.x : (p == 1) ? A.y : (p == 2) ? A.z : A.w;
    v6 = (p == 0) ? A.y : (p == 1) ? A.z : (p == 2) ? A.w : Bv.x;
    v7 = (p == 0) ? A.z : (p == 1) ? A.w : (p == 2) ? Bv.x : Bv.y;
    v8 = (p == 0) ? A.w : (p == 1) ? Bv.x : (p == 2) ? Bv.y : Bv.z;
}

__device__ __forceinline__ void scatter(char* smraw, int m,
                                        float v5, float v6, float v7, float v8)
{
    float* scoord = (float*)(smraw + OFF_COORD);
    short* sbond  = (short*)(smraw + OFF_SBOND);
    short* sang   = (short*)(smraw + OFF_SANG);
    short* stor   = (short*)(smraw + OFF_STOR);
    if (m < N_COORD) scoord[m] = v5;
    if (m < N_BOND)  sbond[m]  = (short)v6;
    if (m < N_ANGW)  sang[m]   = (short)v7;
    if (m < N_TORW)  stor[m]   = (short)v8;
}

__global__ __launch_bounds__(NTHR)
void energy_kernel(const float* __restrict__ feats,
                   const int*   __restrict__ lengths,
                   const float* __restrict__ opt,
                   const float* __restrict__ btype,
                   const float* __restrict__ atype,
                   const float* __restrict__ ttype,
                   float*       __restrict__ out)
{
    extern __shared__ char smraw[];
    float* scoord = (float*)(smraw + OFF_COORD);
    float* swarp  = (float*)(smraw + OFF_WARP);
    float* bk     = (float*)(smraw + OFF_BK);
    float* br0    = (float*)(smraw + OFF_BR0);
    float* ak     = (float*)(smraw + OFF_AK);
    float* at0    = (float*)(smraw + OFF_AT0);
    float* tk     = (float*)(smraw + OFF_TK);
    float* tc0    = (float*)(smraw + OFF_TC0);
    float* ts0    = (float*)(smraw + OFF_TS0);
    float* tn     = (float*)(smraw + OFF_TN);
    short* sbond  = (short*)(smraw + OFF_SBOND);
    short* sang   = (short*)(smraw + OFF_SANG);
    short* stor   = (short*)(smraw + OFF_STOR);

    const int b   = blockIdx.x;
    const int tid = threadIdx.x;
    const float4* f4 = (const float4*)(feats + (size_t)b * NWORDS);

    // ---- per-type param tables (reads only globals; barrier comes later) ----
    if (tid < NBT) {
        int row = (int)btype[tid];
        bk[tid]  = opt[row * 3 + 0];
        br0[tid] = opt[row * 3 + 1];
    } else if (tid < NBT + NAT) {
        int q = tid - NBT;
        int row = (int)atype[q];
        ak[q]  = opt[row * 3 + 0];
        at0[q] = opt[row * 3 + 1];
    } else if (tid < NBT + NAT + NTT) {
        int q = tid - NBT - NAT;
        int row = (int)ttype[q];
        tk[q] = opt[row * 3 + 0];
        float p0 = opt[row * 3 + 1];
        float s, c;
        sincosf(p0, &s, &c);
        tc0[q] = c;
        ts0[q] = s;
        tn[q]  = opt[row * 3 + 2];
    }

    // ---- record-centric extraction, 4 records in flight per thread ----
    for (int m0 = tid; m0 < MAXLEN; m0 += 4 * NTHR) {
        float4 A[4], Bv[4];
        int   mm[4];
        bool  ok[4];
        #pragma unroll
        for (int u = 0; u < 4; u++) {
            mm[u] = m0 + u * NTHR;
            ok[u] = (mm[u] < MAXLEN);
            int w  = 9 * (ok[u] ? mm[u] : 0) + 5;
            int ai = w >> 2;
            A[u]  = f4[ai];
            Bv[u] = f4[min(ai + 1, NV4 - 1)];
        }
        #pragma unroll
        for (int u = 0; u < 4; u++) {
            if (!ok[u]) break;
            int p = (mm[u] + 1) & 3;       // (9m+5) & 3
            float v5, v6, v7, v8;
            demux(A[u], Bv[u], p, v5, v6, v7, v8);
            scatter(smraw, mm[u], v5, v6, v7, v8);
        }
    }
    __syncthreads();

    const int nb = lengths[b * 9 + 6] / 3;
    const int na = lengths[b * 9 + 7] / 4;
    const int nt = lengths[b * 9 + 8] / 5;

    float acc = 0.0f;

    // ---- bonds: E = k * (r - r0)^2 ----
    for (int t = tid; t < NBONDS; t += NTHR) {
        if (t >= nb) continue;
        int i  = sbond[3 * t + 0];
        int j  = sbond[3 * t + 1];
        int ty = sbond[3 * t + 2];
        float dx = scoord[3 * i + 0] - scoord[3 * j + 0];
        float dy = scoord[3 * i + 1] - scoord[3 * j + 1];
        float dz = scoord[3 * i + 2] - scoord[3 * j + 2];
        float r  = sqrtf(dx * dx + dy * dy + dz * dz + EPSF);
        float d  = r - br0[ty];
        acc += bk[ty] * d * d;
    }

    // ---- angles: E = k * (theta - theta0)^2 ----
    for (int t = tid; t < NANG; t += NTHR) {
        if (t >= na) continue;
        int i  = sang[4 * t + 0];
        int j  = sang[4 * t + 1];
        int k  = sang[4 * t + 2];
        int ty = sang[4 * t + 3];
        float ux = scoord[3 * i + 0] - scoord[3 * j + 0];
        float uy = scoord[3 * i + 1] - scoord[3 * j + 1];
        float uz = scoord[3 * i + 2] - scoord[3 * j + 2];
        float vx = scoord[3 * k + 0] - scoord[3 * j + 0];
        float vy = scoord[3 * k + 1] - scoord[3 * j + 1];
        float vz = scoord[3 * k + 2] - scoord[3 * j + 2];
        float duv = ux * vx + uy * vy + uz * vz;
        float duu = ux * ux + uy * uy + uz * uz;
        float dvv = vx * vx + vy * vy + vz * vz;
        float c   = duv * rsqrtf((duu + EPSF) * (dvv + EPSF));
        c = fminf(fmaxf(c, -1.0f + 1e-6f), 1.0f - 1e-6f);
        float theta = acosf(c);
        float d = theta - at0[ty];
        acc += ak[ty] * d * d;
    }

    // ---- torsions: E = k * (1 + cos(n*phi - phi0)), trig-free fast path ----
    for (int t = tid; t < NTOR; t += NTHR) {
        if (t >= nt) continue;
        int i  = stor[5 * t + 0];
        int j  = stor[5 * t + 1];
        int k  = stor[5 * t + 2];
        int l  = stor[5 * t + 3];
        int ty = stor[5 * t + 4];

        float b1x = scoord[3 * j + 0] - scoord[3 * i + 0];
        float b1y = scoord[3 * j + 1] - scoord[3 * i + 1];
        float b1z = scoord[3 * j + 2] - scoord[3 * i + 2];
        float b2x = scoord[3 * k + 0] - scoord[3 * j + 0];
        float b2y = scoord[3 * k + 1] - scoord[3 * j + 1];
        float b2z = scoord[3 * k + 2] - scoord[3 * j + 2];
        float b3x = scoord[3 * l + 0] - scoord[3 * k + 0];
        float b3y = scoord[3 * l + 1] - scoord[3 * k + 1];
        float b3z = scoord[3 * l + 2] - scoord[3 * k + 2];

        float n1x = b1y * b2z - b1z * b2y;
        float n1y = b1z * b2x - b1x * b2z;
        float n1z = b1x * b2y - b1y * b2x;
        float n2x = b2y * b3z - b2z * b3y;
        float n2y = b2z * b3x - b2x * b3z;
        float n2z = b2x * b3y - b2y * b3x;

        float inv = rsqrtf(b2x * b2x + b2y * b2y + b2z * b2z + EPSF);
        float hx = b2x * inv, hy = b2y * inv, hz = b2z * inv;

        float m1x = n1y * hz - n1z * hy;
        float m1y = n1z * hx - n1x * hz;
        float m1z = n1x * hy - n1y * hx;

        float sy = m1x * n2x + m1y * n2y + m1z * n2z;
        float sx = n1x * n2x + n1y * n2y + n1z * n2z;

        float kk  = tk[ty];
        float c0v = tc0[ty];
        float s0v = ts0[ty];
        float n   = tn[ty];
        int   ni  = (int)n;

        float e;
        if (ni >= 1 && ni <= 3 && n == (float)ni) {
            float r2 = rsqrtf(sx * sx + sy * sy + 1e-30f);
            float c = sx * r2, s = sy * r2;
            float c2 = fmaf(2.0f * c, c, -1.0f);
            float s2 = 2.0f * s * c;
            float c3 = c * fmaf(4.0f, c * c, -3.0f);
            float s3 = s * fmaf(-4.0f, s * s, 3.0f);
            float cn = (ni == 1) ? c : (ni == 2) ? c2 : c3;
            float sn = (ni == 1) ? s : (ni == 2) ? s2 : s3;
            e = cn * c0v + sn * s0v;           // cos(n*phi - phi0)
        } else {
            float phi = atan2f(sy, sx);
            float sp, cp;
            sincosf(n * phi, &sp, &cp);
            e = cp * c0v + sp * s0v;
        }
        acc += kk * (1.0f + e);
    }

    // ---- block reduction (32 warps) ----
    #pragma unroll
    for (int off = 16; off > 0; off >>= 1)
        acc += __shfl_down_sync(0xffffffffu, acc, off);
    if ((tid & 31) == 0) swarp[tid >> 5] = acc;
    __syncthreads();
    if (tid < 32) {
        float v = swarp[tid];
        #pragma unroll
        for (int off = 16; off > 0; off >>= 1)
            v += __shfl_down_sync(0xffffffffu, v, off);
        if (tid == 0) out[b] = v;
    }
}

extern "C" void kernel_launch(void* const* d_in, const int* in_sizes, int n_in,
                              void* d_out, int out_size)
{
    const float* feats   = (const float*)d_in[0];
    const int*   lengths = (const int*)  d_in[1];
    const float* opt     = (const float*)d_in[2];
    const float* btype   = (const float*)d_in[3];
    const float* atype   = (const float*)d_in[4];
    const float* ttype   = (const float*)d_in[5];
    float* out = (float*)d_out;

    cudaFuncSetAttribute(energy_kernel,
                         cudaFuncAttributeMaxDynamicSharedMemorySize, SMEM_BYTES);
    energy_kernel<<<BB, NTHR, SMEM_BYTES>>>(feats, lengths, opt, btype, atype,
                                            ttype, out);
}

// round 8
// speedup vs baseline: 1.1218x; 1.1218x over previous
#include <cuda_runtime.h>

#define BB      256
#define MAXLEN  10000
#define NWORDS  (MAXLEN * 9)        // 90000
#define NV4     (NWORDS / 4)        // 22500
#define NATOMS  2000
#define NBONDS  1999
#define NANG    1998
#define NTOR    1997
#define NBT     50
#define NAT     100
#define NTT     200
#define EPSF    1e-8f
#define NTHR    1024

#define N_COORD (3 * NATOMS)        // 6000 floats
#define N_BOND  (3 * NBONDS)        // 5997 shorts
#define N_ANGW  (4 * NANG)          // 7992 shorts
#define N_TORW  (5 * NTOR)          // 9985 shorts

// dynamic smem byte offsets
#define OFF_COORD 0
#define OFF_WARP  (OFF_COORD + N_COORD * 4)      // 24000
#define OFF_BK    (OFF_WARP + 32 * 4)            // 24128
#define OFF_BR0   (OFF_BK  + NBT * 4)            // 24328
#define OFF_AK    (OFF_BR0 + NBT * 4)            // 24528
#define OFF_AT0   (OFF_AK  + NAT * 4)            // 24928
#define OFF_TK    (OFF_AT0 + NAT * 4)            // 25328
#define OFF_TC0   (OFF_TK  + NTT * 4)            // 26128
#define OFF_TS0   (OFF_TC0 + NTT * 4)            // 26928
#define OFF_TN    (OFF_TS0 + NTT * 4)            // 27728
#define OFF_SBOND (OFF_TN  + NTT * 4)            // 28528
#define OFF_SANG  (OFF_SBOND + N_BOND * 2)       // 40522
#define OFF_STOR  (OFF_SANG  + N_ANGW * 2)       // 56506
#define SMEM_BYTES (OFF_STOR + N_TORW * 2 + 8)   // 76484

__device__ __forceinline__ void demux(const float4& A, const float4& Bv, int p,
                                      float& v5, float& v6, float& v7, float& v8)
{
    v5 = (p == 0) ? A.x : (p == 1) ? A.y : (p == 2) ? A.z : A.w;
    v6 = (p == 0) ? A.y : (p == 1) ? A.z : (p == 2) ? A.w : Bv.x;
    v7 = (p == 0) ? A.z : (p == 1) ? A.w : (p == 2) ? Bv.x : Bv.y;
    v8 = (p == 0) ? A.w : (p == 1) ? Bv.x : (p == 2) ? Bv.y : Bv.z;
}

__device__ __forceinline__ void scatter(char* smraw, int m,
                                        float v5, float v6, float v7, float v8)
{
    float* scoord = (float*)(smraw + OFF_COORD);
    short* sbond  = (short*)(smraw + OFF_SBOND);
    short* sang   = (short*)(smraw + OFF_SANG);
    short* stor   = (short*)(smraw + OFF_STOR);
    if (m < N_COORD) scoord[m] = v5;
    if (m < N_BOND)  sbond[m]  = (short)v6;
    if (m < N_ANGW)  sang[m]   = (short)v7;
    if (m < N_TORW)  stor[m]   = (short)v8;
}

__global__ __launch_bounds__(NTHR, 2)
void energy_kernel(const float* __restrict__ feats,
                   const int*   __restrict__ lengths,
                   const float* __restrict__ opt,
                   const float* __restrict__ btype,
                   const float* __restrict__ atype,
                   const float* __restrict__ ttype,
                   float*       __restrict__ out)
{
    extern __shared__ char smraw[];
    float* scoord = (float*)(smraw + OFF_COORD);
    float* swarp  = (float*)(smraw + OFF_WARP);
    float* bk     = (float*)(smraw + OFF_BK);
    float* br0    = (float*)(smraw + OFF_BR0);
    float* ak     = (float*)(smraw + OFF_AK);
    float* at0    = (float*)(smraw + OFF_AT0);
    float* tk     = (float*)(smraw + OFF_TK);
    float* tc0    = (float*)(smraw + OFF_TC0);
    float* ts0    = (float*)(smraw + OFF_TS0);
    float* tn     = (float*)(smraw + OFF_TN);
    short* sbond  = (short*)(smraw + OFF_SBOND);
    short* sang   = (short*)(smraw + OFF_SANG);
    short* stor   = (short*)(smraw + OFF_STOR);

    const int b   = blockIdx.x;
    const int tid = threadIdx.x;
    const float4* f4 = (const float4*)(feats + (size_t)b * NWORDS);

    // ---- per-type param tables ----
    if (tid < NBT) {
        int row = (int)btype[tid];
        bk[tid]  = opt[row * 3 + 0];
        br0[tid] = opt[row * 3 + 1];
    } else if (tid < NBT + NAT) {
        int q = tid - NBT;
        int row = (int)atype[q];
        ak[q]  = opt[row * 3 + 0];
        at0[q] = opt[row * 3 + 1];
    } else if (tid < NBT + NAT + NTT) {
        int q = tid - NBT - NAT;
        int row = (int)ttype[q];
        tk[q] = opt[row * 3 + 0];
        float p0 = opt[row * 3 + 1];
        float s, c;
        sincosf(p0, &s, &c);
        tc0[q] = c;
        ts0[q] = s;
        tn[q]  = opt[row * 3 + 2];
    }

    // ---- record-centric extraction, 2 records in flight per thread ----
    for (int m = tid; m < MAXLEN; m += 2 * NTHR) {
        int m2 = m + NTHR;
        bool has2 = (m2 < MAXLEN);

        int w0 = 9 * m + 5;
        int ai = w0 >> 2;
        float4 A1 = f4[ai];
        float4 B1 = f4[min(ai + 1, NV4 - 1)];

        float4 A2, B2;
        int p2 = 0;
        if (has2) {
            int w2 = 9 * m2 + 5;
            int a2 = w2 >> 2;
            A2 = f4[a2];
            B2 = f4[min(a2 + 1, NV4 - 1)];
            p2 = w2 & 3;
        }

        float v5, v6, v7, v8;
        demux(A1, B1, w0 & 3, v5, v6, v7, v8);
        scatter(smraw, m, v5, v6, v7, v8);

        if (has2) {
            demux(A2, B2, p2, v5, v6, v7, v8);
            scatter(smraw, m2, v5, v6, v7, v8);
        }
    }
    __syncthreads();

    const int nb = lengths[b * 9 + 6] / 3;
    const int na = lengths[b * 9 + 7] / 4;
    const int nt = lengths[b * 9 + 8] / 5;

    float acc = 0.0f;

    // ---- bonds: E = k * (r - r0)^2 ----
    for (int t = tid; t < NBONDS; t += NTHR) {
        if (t >= nb) continue;
        int i  = sbond[3 * t + 0];
        int j  = sbond[3 * t + 1];
        int ty = sbond[3 * t + 2];
        float dx = scoord[3 * i + 0] - scoord[3 * j + 0];
        float dy = scoord[3 * i + 1] - scoord[3 * j + 1];
        float dz = scoord[3 * i + 2] - scoord[3 * j + 2];
        float r  = sqrtf(dx * dx + dy * dy + dz * dz + EPSF);
        float d  = r - br0[ty];
        acc += bk[ty] * d * d;
    }

    // ---- angles: E = k * (theta - theta0)^2 ----
    for (int t = tid; t < NANG; t += NTHR) {
        if (t >= na) continue;
        int i  = sang[4 * t + 0];
        int j  = sang[4 * t + 1];
        int k  = sang[4 * t + 2];
        int ty = sang[4 * t + 3];
        float ux = scoord[3 * i + 0] - scoord[3 * j + 0];
        float uy = scoord[3 * i + 1] - scoord[3 * j + 1];
        float uz = scoord[3 * i + 2] - scoord[3 * j + 2];
        float vx = scoord[3 * k + 0] - scoord[3 * j + 0];
        float vy = scoord[3 * k + 1] - scoord[3 * j + 1];
        float vz = scoord[3 * k + 2] - scoord[3 * j + 2];
        float duv = ux * vx + uy * vy + uz * vz;
        float duu = ux * ux + uy * uy + uz * uz;
        float dvv = vx * vx + vy * vy + vz * vz;
        float c   = duv * rsqrtf((duu + EPSF) * (dvv + EPSF));
        c = fminf(fmaxf(c, -1.0f + 1e-6f), 1.0f - 1e-6f);
        float theta = acosf(c);
        float d = theta - at0[ty];
        acc += ak[ty] * d * d;
    }

    // ---- torsions: E = k*(1 + cos(n*phi - phi0)), trig-free (n in {1,2,3}) ----
    for (int t = tid; t < NTOR; t += NTHR) {
        if (t >= nt) continue;
        int i  = stor[5 * t + 0];
        int j  = stor[5 * t + 1];
        int k  = stor[5 * t + 2];
        int l  = stor[5 * t + 3];
        int ty = stor[5 * t + 4];

        float b1x = scoord[3 * j + 0] - scoord[3 * i + 0];
        float b1y = scoord[3 * j + 1] - scoord[3 * i + 1];
        float b1z = scoord[3 * j + 2] - scoord[3 * i + 2];
        float b2x = scoord[3 * k + 0] - scoord[3 * j + 0];
        float b2y = scoord[3 * k + 1] - scoord[3 * j + 1];
        float b2z = scoord[3 * k + 2] - scoord[3 * j + 2];
        float b3x = scoord[3 * l + 0] - scoord[3 * k + 0];
        float b3y = scoord[3 * l + 1] - scoord[3 * k + 1];
        float b3z = scoord[3 * l + 2] - scoord[3 * k + 2];

        float n1x = b1y * b2z - b1z * b2y;
        float n1y = b1z * b2x - b1x * b2z;
        float n1z = b1x * b2y - b1y * b2x;
        float n2x = b2y * b3z - b2z * b3y;
        float n2y = b2z * b3x - b2x * b3z;
        float n2z = b2x * b3y - b2y * b3x;

        float inv = rsqrtf(b2x * b2x + b2y * b2y + b2z * b2z + EPSF);
        float hx = b2x * inv, hy = b2y * inv, hz = b2z * inv;

        float m1x = n1y * hz - n1z * hy;
        float m1y = n1z * hx - n1x * hz;
        float m1z = n1x * hy - n1y * hx;

        float sy = m1x * n2x + m1y * n2y + m1z * n2z;
        float sx = n1x * n2x + n1y * n2y + n1z * n2z;

        // cos/sin of phi without atan2
        float r2 = rsqrtf(sx * sx + sy * sy + 1e-30f);
        float c = sx * r2, s = sy * r2;
        int ni = (int)tn[ty];
        // n=1: (c,s); n=2: (2c^2-1, 2sc); n=3: (c(4c^2-3), s(3-4s^2))
        float c2 = fmaf(2.0f * c, c, -1.0f);
        float s2 = 2.0f * s * c;
        float cn = (ni == 1) ? c : (ni == 2) ? c2 : c * fmaf(4.0f, c * c, -3.0f);
        float sn = (ni == 1) ? s : (ni == 2) ? s2 : s * fmaf(-4.0f, s * s, 3.0f);
        float e = cn * tc0[ty] + sn * ts0[ty];   // cos(n*phi - phi0)
        acc += tk[ty] * (1.0f + e);
    }

    // ---- block reduction (32 warps) ----
    #pragma unroll
    for (int off = 16; off > 0; off >>= 1)
        acc += __shfl_down_sync(0xffffffffu, acc, off);
    if ((tid & 31) == 0) swarp[tid >> 5] = acc;
    __syncthreads();
    if (tid < 32) {
        float v = swarp[tid];
        #pragma unroll
        for (int off = 16; off > 0; off >>= 1)
            v += __shfl_down_sync(0xffffffffu, v, off);
        if (tid == 0) out[b] = v;
    }
}

extern "C" void kernel_launch(void* const* d_in, const int* in_sizes, int n_in,
                              void* d_out, int out_size)
{
    const float* feats   = (const float*)d_in[0];
    const int*   lengths = (const int*)  d_in[1];
    const float* opt     = (const float*)d_in[2];
    const float* btype   = (const float*)d_in[3];
    const float* atype   = (const float*)d_in[4];
    const float* ttype   = (const float*)d_in[5];
    float* out = (float*)d_out;

    cudaFuncSetAttribute(energy_kernel,
                         cudaFuncAttributeMaxDynamicSharedMemorySize, SMEM_BYTES);
    energy_kernel<<<BB, NTHR, SMEM_BYTES>>>(feats, lengths, opt, btype, atype,
                                            ttype, out);
}

// round 10
// speedup vs baseline: 1.1471x; 1.0225x over previous
#include <cuda_runtime.h>
#include <cstdint>

#define BB      256
#define MAXLEN  10000
#define NWORDS  (MAXLEN * 9)        // 90000
#define NV4     (NWORDS / 4)        // 22500
#define NATOMS  2000
#define NBONDS  1999
#define NANG    1998
#define NTOR    1997
#define NBT     50
#define NAT     100
#define NTT     200
#define EPSF    1e-8f
#define NTHR    1024
#define RB      7500                // record boundary: divisible by 3,4,5

#define N_COORD (3 * NATOMS)        // 6000
#define N_BOND  (3 * NBONDS)        // 5997
#define N_ANGW  (4 * NANG)          // 7992
#define N_TORW  (5 * NTOR)          // 9985
#define N_ANGT  (N_ANGW - RB)       // 492 tail angle words
#define N_TORT  (N_TORW - RB)       // 2485 tail torsion words
#define ANG_SPLIT (RB / 4)          // 1875
#define TOR_SPLIT (RB / 5)          // 1500

// dynamic smem byte offsets
#define OFF_COORD 0
#define OFF_WARP  (OFF_COORD + N_COORD * 4)      // 24000
#define OFF_BK    (OFF_WARP + 32 * 4)            // 24128
#define OFF_BR0   (OFF_BK  + NBT * 4)
#define OFF_AK    (OFF_BR0 + NBT * 4)
#define OFF_AT0   (OFF_AK  + NAT * 4)
#define OFF_TK    (OFF_AT0 + NAT * 4)
#define OFF_TC0   (OFF_TK  + NTT * 4)
#define OFF_TS0   (OFF_TC0 + NTT * 4)
#define OFF_TN    (OFF_TS0 + NTT * 4)
#define OFF_SBOND (OFF_TN  + NTT * 4)            // 28528
#define OFF_SANG  (OFF_SBOND + N_BOND * 2)       // 40522
#define OFF_STOR  (OFF_SANG  + RB * 2)           // 55522
#define OFF_ANGT  (OFF_STOR  + RB * 2 + 2)       // 70524 (4-aligned)
#define OFF_TORT  (OFF_ANGT  + N_ANGT * 4)       // 72492
#define SMEM_BYTES (OFF_TORT + N_TORT * 4 + 8)   // ~82440

#define CP_ASYNC4(dst_u32, src_ptr) \
    asm volatile("cp.async.ca.shared.global [%0], [%1], 4;" \
                 :: "r"(dst_u32), "l"(src_ptr))

__device__ __forceinline__ void demux(const float4& A, const float4& Bv, int p,
                                      float& v5, float& v6, float& v7, float& v8)
{
    v5 = (p == 0) ? A.x : (p == 1) ? A.y : (p == 2) ? A.z : A.w;
    v6 = (p == 0) ? A.y : (p == 1) ? A.z : (p == 2) ? A.w : Bv.x;
    v7 = (p == 0) ? A.z : (p == 1) ? A.w : (p == 2) ? Bv.x : Bv.y;
    v8 = (p == 0) ? A.w : (p == 1) ? Bv.x : (p == 2) ? Bv.y : Bv.z;
}

__device__ __forceinline__ void scatter(char* smraw, int m,
                                        float v5, float v6, float v7, float v8)
{
    float* scoord = (float*)(smraw + OFF_COORD);
    short* sbond  = (short*)(smraw + OFF_SBOND);
    short* sang   = (short*)(smraw + OFF_SANG);
    short* stor   = (short*)(smraw + OFF_STOR);
    if (m < N_COORD) scoord[m] = v5;
    if (m < N_BOND)  sbond[m]  = (short)v6;
    sang[m] = (short)v7;   // m < RB < N_ANGW always valid
    stor[m] = (short)v8;   // m < RB < N_TORW always valid
}

__device__ __forceinline__ float angle_term(const float* scoord,
                                            const float* ak, const float* at0,
                                            int i, int j, int k, int ty)
{
    float ux = scoord[3 * i + 0] - scoord[3 * j + 0];
    float uy = scoord[3 * i + 1] - scoord[3 * j + 1];
    float uz = scoord[3 * i + 2] - scoord[3 * j + 2];
    float vx = scoord[3 * k + 0] - scoord[3 * j + 0];
    float vy = scoord[3 * k + 1] - scoord[3 * j + 1];
    float vz = scoord[3 * k + 2] - scoord[3 * j + 2];
    float duv = ux * vx + uy * vy + uz * vz;
    float duu = ux * ux + uy * uy + uz * uz;
    float dvv = vx * vx + vy * vy + vz * vz;
    float c   = duv * rsqrtf((duu + EPSF) * (dvv + EPSF));
    c = fminf(fmaxf(c, -1.0f + 1e-6f), 1.0f - 1e-6f);
    float theta = acosf(c);
    float d = theta - at0[ty];
    return ak[ty] * d * d;
}

__device__ __forceinline__ float torsion_term(const float* scoord,
                                              const float* tk, const float* tc0,
                                              const float* ts0, const float* tn,
                                              int i, int j, int k, int l, int ty)
{
    float b1x = scoord[3 * j + 0] - scoord[3 * i + 0];
    float b1y = scoord[3 * j + 1] - scoord[3 * i + 1];
    float b1z = scoord[3 * j + 2] - scoord[3 * i + 2];
    float b2x = scoord[3 * k + 0] - scoord[3 * j + 0];
    float b2y = scoord[3 * k + 1] - scoord[3 * j + 1];
    float b2z = scoord[3 * k + 2] - scoord[3 * j + 2];
    float b3x = scoord[3 * l + 0] - scoord[3 * k + 0];
    float b3y = scoord[3 * l + 1] - scoord[3 * k + 1];
    float b3z = scoord[3 * l + 2] - scoord[3 * k + 2];

    float n1x = b1y * b2z - b1z * b2y;
    float n1y = b1z * b2x - b1x * b2z;
    float n1z = b1x * b2y - b1y * b2x;
    float n2x = b2y * b3z - b2z * b3y;
    float n2y = b2z * b3x - b2x * b3z;
    float n2z = b2x * b3y - b2y * b3x;

    float inv = rsqrtf(b2x * b2x + b2y * b2y + b2z * b2z + EPSF);
    float hx = b2x * inv, hy = b2y * inv, hz = b2z * inv;

    float m1x = n1y * hz - n1z * hy;
    float m1y = n1z * hx - n1x * hz;
    float m1z = n1x * hy - n1y * hx;

    float sy = m1x * n2x + m1y * n2y + m1z * n2z;
    float sx = n1x * n2x + n1y * n2y + n1z * n2z;

    float r2 = rsqrtf(sx * sx + sy * sy + 1e-30f);
    float c = sx * r2, s = sy * r2;
    int ni = (int)tn[ty];
    float c2 = fmaf(2.0f * c, c, -1.0f);
    float s2 = 2.0f * s * c;
    float cn = (ni == 1) ? c : (ni == 2) ? c2 : c * fmaf(4.0f, c * c, -3.0f);
    float sn = (ni == 1) ? s : (ni == 2) ? s2 : s * fmaf(-4.0f, s * s, 3.0f);
    float e = cn * tc0[ty] + sn * ts0[ty];
    return tk[ty] * (1.0f + e);
}

__global__ __launch_bounds__(NTHR, 2)
void energy_kernel(const float* __restrict__ feats,
                   const int*   __restrict__ lengths,
                   const float* __restrict__ opt,
                   const float* __restrict__ btype,
                   const float* __restrict__ atype,
                   const float* __restrict__ ttype,
                   float*       __restrict__ out)
{
    extern __shared__ char smraw[];
    float* scoord = (float*)(smraw + OFF_COORD);
    float* swarp  = (float*)(smraw + OFF_WARP);
    float* bk     = (float*)(smraw + OFF_BK);
    float* br0    = (float*)(smraw + OFF_BR0);
    float* ak     = (float*)(smraw + OFF_AK);
    float* at0    = (float*)(smraw + OFF_AT0);
    float* tk     = (float*)(smraw + OFF_TK);
    float* tc0    = (float*)(smraw + OFF_TC0);
    float* ts0    = (float*)(smraw + OFF_TS0);
    float* tn     = (float*)(smraw + OFF_TN);
    short* sbond  = (short*)(smraw + OFF_SBOND);
    short* sang   = (short*)(smraw + OFF_SANG);
    short* stor   = (short*)(smraw + OFF_STOR);
    float* angt   = (float*)(smraw + OFF_ANGT);
    float* tort   = (float*)(smraw + OFF_TORT);

    const int b   = blockIdx.x;
    const int tid = threadIdx.x;
    const float* fb = feats + (size_t)b * NWORDS;
    const float4* f4 = (const float4*)fb;

    // ---- per-type param tables ----
    if (tid < NBT) {
        int row = (int)btype[tid];
        bk[tid]  = opt[row * 3 + 0];
        br0[tid] = opt[row * 3 + 1];
    } else if (tid < NBT + NAT) {
        int q = tid - NBT;
        int row = (int)atype[q];
        ak[q]  = opt[row * 3 + 0];
        at0[q] = opt[row * 3 + 1];
    } else if (tid < NBT + NAT + NTT) {
        int q = tid - NBT - NAT;
        int row = (int)ttype[q];
        tk[q] = opt[row * 3 + 0];
        float p0 = opt[row * 3 + 1];
        float s, c;
        sincosf(p0, &s, &c);
        tc0[q] = c;
        ts0[q] = s;
        tn[q]  = opt[row * 3 + 2];
    }

    // ---- phase 1: extract records [0, RB), 2 in flight per thread ----
    for (int m = tid; m < RB; m += 2 * NTHR) {
        int m2 = m + NTHR;
        bool has2 = (m2 < RB);

        int w0 = 9 * m + 5;
        int ai = w0 >> 2;
        float4 A1 = f4[ai];
        float4 B1 = f4[ai + 1];        // m < RB so ai+1 <= 16877 < NV4

        float4 A2, B2;
        int p2 = 0;
        if (has2) {
            int w2 = 9 * m2 + 5;
            int a2 = w2 >> 2;
            A2 = f4[a2];
            B2 = f4[a2 + 1];
            p2 = w2 & 3;
        }

        float v5, v6, v7, v8;
        demux(A1, B1, w0 & 3, v5, v6, v7, v8);
        scatter(smraw, m, v5, v6, v7, v8);

        if (has2) {
            demux(A2, B2, p2, v5, v6, v7, v8);
            scatter(smraw, m2, v5, v6, v7, v8);
        }
    }

    // ---- kick off async tail copies: records [RB, MAXLEN), cols 7 & 8 ----
    {
        unsigned int angt_a = (unsigned int)__cvta_generic_to_shared(angt);
        unsigned int tort_a = (unsigned int)__cvta_generic_to_shared(tort);
        for (int m = RB + tid; m < MAXLEN; m += NTHR) {
            const float* src = fb + 9 * m;
            int o = m - RB;
            if (m < N_ANGW) CP_ASYNC4(angt_a + o * 4, src + 7);
            if (m < N_TORW) CP_ASYNC4(tort_a + o * 4, src + 8);
        }
        asm volatile("cp.async.commit_group;");
    }
    __syncthreads();   // head smem visible; tail still streaming

    const int nb = lengths[b * 9 + 6] / 3;
    const int na = lengths[b * 9 + 7] / 4;
    const int nt = lengths[b * 9 + 8] / 5;

    float acc = 0.0f;

    // ---- compute-partial (depends only on records < RB) ----
    for (int t = tid; t < NBONDS; t += NTHR) {
        if (t >= nb) continue;
        int i  = sbond[3 * t + 0];
        int j  = sbond[3 * t + 1];
        int ty = sbond[3 * t + 2];
        float dx = scoord[3 * i + 0] - scoord[3 * j + 0];
        float dy = scoord[3 * i + 1] - scoord[3 * j + 1];
        float dz = scoord[3 * i + 2] - scoord[3 * j + 2];
        float r  = sqrtf(dx * dx + dy * dy + dz * dz + EPSF);
        float d  = r - br0[ty];
        acc += bk[ty] * d * d;
    }

    for (int t = tid; t < ANG_SPLIT; t += NTHR) {
        if (t >= na) continue;
        acc += angle_term(scoord, ak, at0,
                          sang[4 * t + 0], sang[4 * t + 1],
                          sang[4 * t + 2], sang[4 * t + 3]);
    }

    for (int t = tid; t < TOR_SPLIT; t += NTHR) {
        if (t >= nt) continue;
        acc += torsion_term(scoord, tk, tc0, ts0, tn,
                            stor[5 * t + 0], stor[5 * t + 1],
                            stor[5 * t + 2], stor[5 * t + 3],
                            stor[5 * t + 4]);
    }

    // ---- wait for tail stream, then finish remaining terms ----
    asm volatile("cp.async.wait_group 0;");
    __syncthreads();

    for (int t = ANG_SPLIT + tid; t < NANG; t += NTHR) {
        if (t >= na) continue;
        int base = 4 * t - RB;
        acc += angle_term(scoord, ak, at0,
                          (int)angt[base + 0], (int)angt[base + 1],
                          (int)angt[base + 2], (int)angt[base + 3]);
    }

    for (int t = TOR_SPLIT + tid; t < NTOR; t += NTHR) {
        if (t >= nt) continue;
        int base = 5 * t - RB;
        acc += torsion_term(scoord, tk, tc0, ts0, tn,
                            (int)tort[base + 0], (int)tort[base + 1],
                            (int)tort[base + 2], (int)tort[base + 3],
                            (int)tort[base + 4]);
    }

    // ---- block reduction (32 warps) ----
    #pragma unroll
    for (int off = 16; off > 0; off >>= 1)
        acc += __shfl_down_sync(0xffffffffu, acc, off);
    if ((tid & 31) == 0) swarp[tid >> 5] = acc;
    __syncthreads();
    if (tid < 32) {
        float v = swarp[tid];
        #pragma unroll
        for (int off = 16; off > 0; off >>= 1)
            v += __shfl_down_sync(0xffffffffu, v, off);
        if (tid == 0) out[b] = v;
    }
}

extern "C" void kernel_launch(void* const* d_in, const int* in_sizes, int n_in,
                              void* d_out, int out_size)
{
    const float* feats   = (const float*)d_in[0];
    const int*   lengths = (const int*)  d_in[1];
    const float* opt     = (const float*)d_in[2];
    const float* btype   = (const float*)d_in[3];
    const float* atype   = (const float*)d_in[4];
    const float* ttype   = (const float*)d_in[5];
    float* out = (float*)d_out;

    cudaFuncSetAttribute(energy_kernel,
                         cudaFuncAttributeMaxDynamicSharedMemorySize, SMEM_BYTES);
    energy_kernel<<<BB, NTHR, SMEM_BYTES>>>(feats, lengths, opt, btype, atype,
                                            ttype, out);
}